// round 6
// baseline (speedup 1.0000x reference)
#include <cuda_runtime.h>
#include <cuda_bf16.h>
#include <mma.h>
#include <cstdint>

using namespace nvcuda;

// Problem constants
#define BB   4
#define SS   2048
#define DIMM 2048
#define HH   16
#define HDD  128
#define MM   (BB*SS)            // 8192
#define SCALE 0.08838834764831845f   // 1/sqrt(128)
#define BIGNEG (-1e30f)

// ---------------- scratch (__device__ globals: allocation-free) -------------
__device__ float g_qt [MM*DIMM];   // Q normed+roped, (B,H,S,HD)
__device__ float g_kt [MM*DIMM];   // K normed+roped, (B,H,S,HD)
__device__ float g_v  [MM*DIMM];   // V projection,   (B,S,DIM)
__device__ float g_at [MM*DIMM];   // attention out,  (B,S,DIM)

__device__ __forceinline__ float to_tf32(float x) {
    uint32_t u;
    asm("cvt.rna.tf32.f32 %0, %1;" : "=r"(u) : "f"(x));
    return __uint_as_float(u);
}
__device__ __forceinline__ uint32_t smem_u32(const void* p) {
    return (uint32_t)__cvta_generic_to_shared(p);
}
#define CP16(dst, src) asm volatile("cp.async.cg.shared.global [%0], [%1], 16;" \
                                    :: "r"(dst), "l"(src))
#define CPC()  asm volatile("cp.async.commit_group;")
#define CPW1() asm volatile("cp.async.wait_group 1;")

// =============================== GEMM core ==================================
// C[M,N] = A[M,K] @ W[N,K]^T  (M=8192, N=K=2048), TF32 wmma m16n16k8.
// Block 128x128x32, 256 threads (8 warps 4x2, warp 32x64).
// cp.async double-buffered smem pipeline; rna-tf32 applied on fragment regs.
#define G_BM 128
#define G_BN 128
#define G_BK 32
#define G_LD 36                    // padded smem ld (36 mod 32 = 4)
#define G_BUF (G_BM * G_LD)        // 4608 floats per tile buffer
#define G_SMEM_BYTES (4 * G_BUF * 4)   // 73728 B (A0,B0,A1,B1)
#define G_NT (DIMM / G_BK)         // 64

#define GEMM_BODY(A_, W_)                                                      \
    extern __shared__ float dsm[];                                             \
    float* As[2] = { dsm,         dsm + 2 * G_BUF };                           \
    float* Bs[2] = { dsm + G_BUF, dsm + 3 * G_BUF };                           \
    const int bm = blockIdx.y * G_BM;                                          \
    const int bn = blockIdx.x * G_BN;                                          \
    const int tid = threadIdx.x;                                               \
    const int warp = tid >> 5;                                                 \
    const int wm = warp >> 1;                                                  \
    const int wn = warp & 1;                                                   \
    const int lr = tid >> 3;                                                   \
    const int lc = (tid & 7) << 2;                                             \
    wmma::fragment<wmma::accumulator, 16, 16, 8, float> acc[2][4];             \
    _Pragma("unroll")                                                          \
    for (int i = 0; i < 2; i++)                                                \
        _Pragma("unroll")                                                      \
        for (int j = 0; j < 4; j++) wmma::fill_fragment(acc[i][j], 0.0f);      \
    _Pragma("unroll")                                                          \
    for (int p = 0; p < 4; p++) {                                              \
        CP16(smem_u32(&As[0][(lr + p * 32) * G_LD + lc]),                      \
             &A_[(bm + lr + p * 32) * DIMM + lc]);                             \
        CP16(smem_u32(&Bs[0][(lr + p * 32) * G_LD + lc]),                      \
             &W_[(bn + lr + p * 32) * DIMM + lc]);                             \
    }                                                                          \
    CPC();                                                                     \
    for (int it = 0; it < G_NT; it++) {                                        \
        if (it + 1 < G_NT) {                                                   \
            const int nb = (it + 1) & 1;                                       \
            const int k0 = (it + 1) * G_BK;                                    \
            _Pragma("unroll")                                                  \
            for (int p = 0; p < 4; p++) {                                      \
                CP16(smem_u32(&As[nb][(lr + p * 32) * G_LD + lc]),             \
                     &A_[(bm + lr + p * 32) * DIMM + k0 + lc]);                \
                CP16(smem_u32(&Bs[nb][(lr + p * 32) * G_LD + lc]),             \
                     &W_[(bn + lr + p * 32) * DIMM + k0 + lc]);                \
            }                                                                  \
        }                                                                      \
        CPC(); CPW1(); __syncthreads();                                        \
        const float* Ac = As[it & 1];                                          \
        const float* Bc = Bs[it & 1];                                          \
        _Pragma("unroll")                                                      \
        for (int kk = 0; kk < G_BK; kk += 8) {                                 \
            wmma::fragment<wmma::matrix_a, 16, 16, 8, wmma::precision::tf32,   \
                           wmma::row_major> af[2];                             \
            wmma::fragment<wmma::matrix_b, 16, 16, 8, wmma::precision::tf32,   \
                           wmma::col_major> bf[4];                             \
            _Pragma("unroll")                                                  \
            for (int i = 0; i < 2; i++) {                                      \
                wmma::load_matrix_sync(af[i],                                  \
                    &Ac[(wm * 32 + i * 16) * G_LD + kk], G_LD);                \
                _Pragma("unroll")                                              \
                for (int e = 0; e < af[i].num_elements; e++)                   \
                    af[i].x[e] = to_tf32(af[i].x[e]);                          \
            }                                                                  \
            _Pragma("unroll")                                                  \
            for (int j = 0; j < 4; j++) {                                      \
                wmma::load_matrix_sync(bf[j],                                  \
                    &Bc[(wn * 64 + j * 16) * G_LD + kk], G_LD);                \
                _Pragma("unroll")                                              \
                for (int e = 0; e < bf[j].num_elements; e++)                   \
                    bf[j].x[e] = to_tf32(bf[j].x[e]);                          \
            }                                                                  \
            _Pragma("unroll")                                                  \
            for (int i = 0; i < 2; i++)                                        \
                _Pragma("unroll")                                              \
                for (int j = 0; j < 4; j++)                                    \
                    wmma::mma_sync(acc[i][j], af[i], bf[j], acc[i][j]);        \
        }                                                                      \
        __syncthreads();                                                       \
    }

// ---- plain GEMM: X @ Wv^T -> g_v (B,S,DIM) ----
__global__ __launch_bounds__(256, 2) void gemm_v(const float* __restrict__ A,
                                                 const float* __restrict__ W) {
    GEMM_BODY(A, W)
#pragma unroll
    for (int i = 0; i < 2; i++)
#pragma unroll
        for (int j = 0; j < 4; j++)
            wmma::store_matrix_sync(
                &g_v[(bm + wm * 32 + i * 16) * DIMM + bn + wn * 64 + j * 16],
                acc[i][j], DIMM, wmma::mem_row_major);
}

// ---- plain GEMM: g_at @ Wo^T -> out ----
__global__ __launch_bounds__(256, 2) void gemm_out(const float* __restrict__ W,
                                                   float* __restrict__ C) {
    const float* A = g_at;
    GEMM_BODY(A, W)
#pragma unroll
    for (int i = 0; i < 2; i++)
#pragma unroll
        for (int j = 0; j < 4; j++)
            wmma::store_matrix_sync(
                &C[(bm + wm * 32 + i * 16) * DIMM + bn + wn * 64 + j * 16],
                acc[i][j], DIMM, wmma::mem_row_major);
}

// ---- fused GEMM + RMSNorm + RoPE + transpose for Q/K ----
// 128-wide column tile == one head (HD=128): full head row is in this C tile.
#define C_LD 132

__global__ __launch_bounds__(256, 2) void gemm_qk(const float* __restrict__ A,
                                                  const float* __restrict__ W,
                                                  const float* __restrict__ nw,
                                                  const float* __restrict__ ct,
                                                  const float* __restrict__ st,
                                                  int which) {
    GEMM_BODY(A, W)

    // Mainloop ends with __syncthreads(): safe to overwrite buffers with C.
    float* Cs = dsm;               // 128*132 = 16896 floats <= 18432 available
#pragma unroll
    for (int i = 0; i < 2; i++)
#pragma unroll
        for (int j = 0; j < 4; j++)
            wmma::store_matrix_sync(&Cs[(wm * 32 + i * 16) * C_LD + wn * 64 + j * 16],
                                    acc[i][j], C_LD, wmma::mem_row_major);
    __syncthreads();

    const int lane = tid & 31;
    const int h = bn >> 7;
    const float4 wv4 = ((const float4*)nw)[lane];
    const float sgn = (lane < 16) ? -1.0f : 1.0f;
    float* dstT = which ? g_kt : g_qt;

#pragma unroll
    for (int i = 0; i < 16; i++) {
        const int r = warp + 8 * i;            // 0..127
        float4 v = *(const float4*)&Cs[r * C_LD + lane * 4];
        float ssum = v.x * v.x + v.y * v.y + v.z * v.z + v.w * v.w;
#pragma unroll
        for (int o = 16; o; o >>= 1) ssum += __shfl_xor_sync(0xffffffffu, ssum, o);
        const float rinv = rsqrtf(ssum * (1.0f / HDD) + 1e-6f);

        float n0 = v.x * rinv * wv4.x;
        float n1 = v.y * rinv * wv4.y;
        float n2 = v.z * rinv * wv4.z;
        float n3 = v.w * rinv * wv4.w;

        float o0 = __shfl_xor_sync(0xffffffffu, n0, 16);
        float o1 = __shfl_xor_sync(0xffffffffu, n1, 16);
        float o2 = __shfl_xor_sync(0xffffffffu, n2, 16);
        float o3 = __shfl_xor_sync(0xffffffffu, n3, 16);

        const int m = bm + r;
        const int b = m >> 11;
        const int s = m & (SS - 1);

        const float4 c4 = ((const float4*)(ct + s * HDD))[lane];
        const float4 s4 = ((const float4*)(st + s * HDD))[lane];
        float4 outv;
        outv.x = n0 * c4.x + sgn * o0 * s4.x;
        outv.y = n1 * c4.y + sgn * o1 * s4.y;
        outv.z = n2 * c4.z + sgn * o2 * s4.z;
        outv.w = n3 * c4.w + sgn * o3 * s4.w;

        ((float4*)&dstT[((b * HH + h) * SS + s) * HDD])[lane] = outv;
    }
}

// ============================ Flash attention ===============================
// TF32 mma.m16n8k8; block = (b,h) x 128 query rows, 8 warps (16 rows each).
// KV tiles of 32, cp.async double-buffered. V kept row-major (ld=136:
// conflict-free gather reads AND conflict-free coalesced stores).
#define F_QT 128
#define F_KT 32
#define F_LQ 132
#define F_LK 132
#define F_LV 136
#define F_LP 36
#define F_KBUF (F_KT * F_LK)                  // 4224
#define F_VBUF (F_KT * F_LV)                  // 4352
#define F_OFF_K (F_QT * F_LQ)                 // 16896
#define F_OFF_V (F_OFF_K + 2 * F_KBUF)        // 25344
#define F_OFF_P (F_OFF_V + 2 * F_VBUF)        // 34048
#define F_SM_FLOATS (F_OFF_P + 8 * 16 * F_LP) // 38656 -> 154624 B

#define MMA_TF32(Cr, a0, a1, a2, a3, b0, b1)                                  \
    asm volatile("mma.sync.aligned.m16n8k8.row.col.f32.tf32.tf32.f32 "        \
                 "{%0,%1,%2,%3}, {%4,%5,%6,%7}, {%8,%9}, {%0,%1,%2,%3};"      \
                 : "+f"(Cr[0]), "+f"(Cr[1]), "+f"(Cr[2]), "+f"(Cr[3])         \
                 : "r"(a0), "r"(a1), "r"(a2), "r"(a3), "r"(b0), "r"(b1))

__global__ __launch_bounds__(256, 1) void flash_attn() {
    extern __shared__ float sm[];
    float* qs = sm;
    float* kbuf[2] = { sm + F_OFF_K, sm + F_OFF_K + F_KBUF };
    float* vbuf[2] = { sm + F_OFF_V, sm + F_OFF_V + F_VBUF };

    const int tid = threadIdx.x;
    const int w = tid >> 5;
    const int lane = tid & 31;
    const int g = lane >> 2;     // 0..7
    const int q = lane & 3;      // 0..3
    const int bh = blockIdx.y;
    const int b = bh >> 4, h = bh & 15;
    const int qt0 = blockIdx.x * F_QT;
    float* pw = sm + F_OFF_P + w * 16 * F_LP;

    // ---- Q tile (128x128) to smem, rna-tf32 ----
    const float* qbase = g_qt + (bh * SS + qt0) * HDD;
#pragma unroll
    for (int p = 0; p < 16; p++) {
        int idx = tid + p * 256;
        int r = idx >> 5, c4 = (idx & 31) << 2;
        float4 vq = *(const float4*)&qbase[r * HDD + c4];
        vq.x = to_tf32(vq.x); vq.y = to_tf32(vq.y);
        vq.z = to_tf32(vq.z); vq.w = to_tf32(vq.w);
        *(float4*)&qs[r * F_LQ + c4] = vq;
    }

    float o[16][4];
#pragma unroll
    for (int nt = 0; nt < 16; nt++)
#pragma unroll
        for (int e = 0; e < 4; e++) o[nt][e] = 0.0f;
    float m0 = BIGNEG, m1 = BIGNEG, l0 = 0.0f, l1 = 0.0f;

    const int row0g = qt0 + w * 16 + g;
    const int row1g = row0g + 8;
    const int nj = 4 * blockIdx.x + 4;

    // ---- prologue: async-load KV tile 0 ----
    {
        const float* kg = g_kt + (bh * SS) * HDD;
        const float* vg = g_v + (b * SS) * DIMM + h * HDD;
#pragma unroll
        for (int p = 0; p < 4; p++) {
            int idx = tid + p * 256;
            int r = idx >> 5, c4 = (idx & 31) << 2;
            CP16(smem_u32(&kbuf[0][r * F_LK + c4]), &kg[r * HDD + c4]);
            CP16(smem_u32(&vbuf[0][r * F_LV + c4]), &vg[r * DIMM + c4]);
        }
    }
    CPC();

    for (int j = 0; j < nj; j++) {
        if (j + 1 < nj) {
            const int nb = (j + 1) & 1;
            const float* kg = g_kt + (bh * SS + (j + 1) * F_KT) * HDD;
            const float* vg = g_v + (b * SS + (j + 1) * F_KT) * DIMM + h * HDD;
#pragma unroll
            for (int p = 0; p < 4; p++) {
                int idx = tid + p * 256;
                int r = idx >> 5, c4 = (idx & 31) << 2;
                CP16(smem_u32(&kbuf[nb][r * F_LK + c4]), &kg[r * HDD + c4]);
                CP16(smem_u32(&vbuf[nb][r * F_LV + c4]), &vg[r * DIMM + c4]);
            }
        }
        CPC(); CPW1(); __syncthreads();
        const float* ks = kbuf[j & 1];
        const float* vs = vbuf[j & 1];

        // ---- S = Q @ K^T : 16 x 32 per warp ----
        float c[4][4];
#pragma unroll
        for (int nt = 0; nt < 4; nt++)
#pragma unroll
            for (int e = 0; e < 4; e++) c[nt][e] = 0.0f;
#pragma unroll
        for (int ks8 = 0; ks8 < 16; ks8++) {
            const int kk = ks8 * 8;
            uint32_t a0 = __float_as_uint(qs[(w * 16 + g)     * F_LQ + kk + q]);
            uint32_t a1 = __float_as_uint(qs[(w * 16 + g + 8) * F_LQ + kk + q]);
            uint32_t a2 = __float_as_uint(qs[(w * 16 + g)     * F_LQ + kk + q + 4]);
            uint32_t a3 = __float_as_uint(qs[(w * 16 + g + 8) * F_LQ + kk + q + 4]);
#pragma unroll
            for (int nt = 0; nt < 4; nt++) {
                uint32_t b0 = __float_as_uint(to_tf32(ks[(nt * 8 + g) * F_LK + kk + q]));
                uint32_t b1 = __float_as_uint(to_tf32(ks[(nt * 8 + g) * F_LK + kk + q + 4]));
                MMA_TF32(c[nt], a0, a1, a2, a3, b0, b1);
            }
        }

        // ---- online softmax ----
        float mx0 = BIGNEG, mx1 = BIGNEG;
        if (j >= 4 * blockIdx.x) {    // diagonal tiles: apply causal mask
#pragma unroll
            for (int nt = 0; nt < 4; nt++) {
                const int cb = j * F_KT + nt * 8 + q * 2;
                c[nt][0] = (cb     <= row0g) ? c[nt][0] * SCALE : BIGNEG;
                c[nt][1] = (cb + 1 <= row0g) ? c[nt][1] * SCALE : BIGNEG;
                c[nt][2] = (cb     <= row1g) ? c[nt][2] * SCALE : BIGNEG;
                c[nt][3] = (cb + 1 <= row1g) ? c[nt][3] * SCALE : BIGNEG;
                mx0 = fmaxf(mx0, fmaxf(c[nt][0], c[nt][1]));
                mx1 = fmaxf(mx1, fmaxf(c[nt][2], c[nt][3]));
            }
        } else {                      // interior tiles: no mask needed
#pragma unroll
            for (int nt = 0; nt < 4; nt++) {
                c[nt][0] *= SCALE; c[nt][1] *= SCALE;
                c[nt][2] *= SCALE; c[nt][3] *= SCALE;
                mx0 = fmaxf(mx0, fmaxf(c[nt][0], c[nt][1]));
                mx1 = fmaxf(mx1, fmaxf(c[nt][2], c[nt][3]));
            }
        }
        mx0 = fmaxf(mx0, __shfl_xor_sync(0xffffffffu, mx0, 1));
        mx0 = fmaxf(mx0, __shfl_xor_sync(0xffffffffu, mx0, 2));
        mx1 = fmaxf(mx1, __shfl_xor_sync(0xffffffffu, mx1, 1));
        mx1 = fmaxf(mx1, __shfl_xor_sync(0xffffffffu, mx1, 2));

        const float mn0 = fmaxf(m0, mx0), mn1 = fmaxf(m1, mx1);
        const float al0 = __expf(m0 - mn0), al1 = __expf(m1 - mn1);
        float sum0 = 0.0f, sum1 = 0.0f;
#pragma unroll
        for (int nt = 0; nt < 4; nt++) {
            c[nt][0] = __expf(c[nt][0] - mn0); sum0 += c[nt][0];
            c[nt][1] = __expf(c[nt][1] - mn0); sum0 += c[nt][1];
            c[nt][2] = __expf(c[nt][2] - mn1); sum1 += c[nt][2];
            c[nt][3] = __expf(c[nt][3] - mn1); sum1 += c[nt][3];
        }
        sum0 += __shfl_xor_sync(0xffffffffu, sum0, 1);
        sum0 += __shfl_xor_sync(0xffffffffu, sum0, 2);
        sum1 += __shfl_xor_sync(0xffffffffu, sum1, 1);
        sum1 += __shfl_xor_sync(0xffffffffu, sum1, 2);
        l0 = l0 * al0 + sum0;
        l1 = l1 * al1 + sum1;
        m0 = mn0; m1 = mn1;
#pragma unroll
        for (int nt = 0; nt < 16; nt++) {
            o[nt][0] *= al0; o[nt][1] *= al0;
            o[nt][2] *= al1; o[nt][3] *= al1;
        }

        // ---- write P (16x32) to per-warp smem, tf32 ----
#pragma unroll
        for (int nt = 0; nt < 4; nt++) {
            pw[g       * F_LP + nt * 8 + q * 2 + 0] = to_tf32(c[nt][0]);
            pw[g       * F_LP + nt * 8 + q * 2 + 1] = to_tf32(c[nt][1]);
            pw[(g + 8) * F_LP + nt * 8 + q * 2 + 0] = to_tf32(c[nt][2]);
            pw[(g + 8) * F_LP + nt * 8 + q * 2 + 1] = to_tf32(c[nt][3]);
        }
        __syncwarp();

        // ---- O += P @ V : 16 x 128 per warp (V row-major gather) ----
#pragma unroll
        for (int ks8 = 0; ks8 < 4; ks8++) {
            const int kk = ks8 * 8;
            uint32_t a0 = __float_as_uint(pw[g       * F_LP + kk + q]);
            uint32_t a1 = __float_as_uint(pw[(g + 8) * F_LP + kk + q]);
            uint32_t a2 = __float_as_uint(pw[g       * F_LP + kk + q + 4]);
            uint32_t a3 = __float_as_uint(pw[(g + 8) * F_LP + kk + q + 4]);
#pragma unroll
            for (int nt = 0; nt < 16; nt++) {
                uint32_t b0 = __float_as_uint(to_tf32(vs[(kk + q)     * F_LV + nt * 8 + g]));
                uint32_t b1 = __float_as_uint(to_tf32(vs[(kk + q + 4) * F_LV + nt * 8 + g]));
                MMA_TF32(o[nt], a0, a1, a2, a3, b0, b1);
            }
        }
        __syncthreads();
    }

    // ---- epilogue: O / l -> (B,S,DIM) for the output GEMM ----
    const float inv0 = 1.0f / l0, inv1 = 1.0f / l1;
    float* ob0 = g_at + (b * SS + row0g) * DIMM + h * HDD;
    float* ob1 = g_at + (b * SS + row1g) * DIMM + h * HDD;
#pragma unroll
    for (int nt = 0; nt < 16; nt++) {
        const int d = nt * 8 + q * 2;
        *(float2*)&ob0[d] = make_float2(o[nt][0] * inv0, o[nt][1] * inv0);
        *(float2*)&ob1[d] = make_float2(o[nt][2] * inv1, o[nt][3] * inv1);
    }
}

// =============================== launch =====================================
extern "C" void kernel_launch(void* const* d_in, const int* in_sizes, int n_in,
                              void* d_out, int out_size) {
    (void)in_sizes; (void)n_in; (void)out_size;
    const float* x  = (const float*)d_in[0];
    const float* ct = (const float*)d_in[1];
    const float* st = (const float*)d_in[2];
    // d_in[3] = causal mask — implemented analytically
    const float* wq = (const float*)d_in[4];
    const float* wk = (const float*)d_in[5];
    const float* wv = (const float*)d_in[6];
    const float* wo = (const float*)d_in[7];
    const float* qw = (const float*)d_in[8];
    const float* kw = (const float*)d_in[9];
    float* out = (float*)d_out;

    cudaFuncSetAttribute(gemm_qk,  cudaFuncAttributeMaxDynamicSharedMemorySize, G_SMEM_BYTES);
    cudaFuncSetAttribute(gemm_v,   cudaFuncAttributeMaxDynamicSharedMemorySize, G_SMEM_BYTES);
    cudaFuncSetAttribute(gemm_out, cudaFuncAttributeMaxDynamicSharedMemorySize, G_SMEM_BYTES);
    cudaFuncSetAttribute(flash_attn, cudaFuncAttributeMaxDynamicSharedMemorySize,
                         F_SM_FLOATS * (int)sizeof(float));

    const dim3 gGrid(DIMM / G_BN, MM / G_BM);   // (16, 64)

    gemm_qk<<<gGrid, 256, G_SMEM_BYTES>>>(x, wq, qw, ct, st, 0);
    gemm_qk<<<gGrid, 256, G_SMEM_BYTES>>>(x, wk, kw, ct, st, 1);
    gemm_v <<<gGrid, 256, G_SMEM_BYTES>>>(x, wv);

    flash_attn<<<dim3(SS / F_QT, BB * HH), 256, F_SM_FLOATS * sizeof(float)>>>();

    gemm_out<<<gGrid, 256, G_SMEM_BYTES>>>(wo, out);
}

// round 8
// speedup vs baseline: 1.0684x; 1.0684x over previous
#include <cuda_runtime.h>
#include <cuda_bf16.h>
#include <mma.h>
#include <cstdint>

using namespace nvcuda;

// Problem constants
#define BB   4
#define SS   2048
#define DIMM 2048
#define HH   16
#define HDD  128
#define MM   (BB*SS)            // 8192
#define WSZ  (DIMM*DIMM)        // 4194304
#define SCALE 0.08838834764831845f   // 1/sqrt(128)
#define BIGNEG (-1e30f)

// ---------------- scratch (__device__ globals: allocation-free) -------------
__device__ float g_qt [MM*DIMM];   // Q normed+roped (tf32-rounded), (B,H,S,HD)
__device__ float g_kt [MM*DIMM];   // K normed+roped (tf32-rounded), (B,H,S,HD)
__device__ float g_v  [MM*DIMM];   // V projection   (tf32-rounded), (B,S,DIM)
__device__ float g_at [MM*DIMM];   // phase 1: rounded X; phase 2: attn out (rounded)
__device__ float g_w  [4*WSZ];     // rounded wq,wk,wv,wo

__device__ __forceinline__ float to_tf32(float x) {
    uint32_t u;
    asm("cvt.rna.tf32.f32 %0, %1;" : "=r"(u) : "f"(x));
    return __uint_as_float(u);
}
__device__ __forceinline__ uint32_t smem_u32(const void* p) {
    return (uint32_t)__cvta_generic_to_shared(p);
}
#define CP16(dst, src) asm volatile("cp.async.cg.shared.global [%0], [%1], 16;" \
                                    :: "r"(dst), "l"(src))
#define CPC()  asm volatile("cp.async.commit_group;")
#define CPW1() asm volatile("cp.async.wait_group 1;")

// ---------------- prepass: rna-tf32 rounding copy ---------------------------
__global__ __launch_bounds__(256) void round_copy(const float* __restrict__ s,
                                                  float* __restrict__ d, int n4) {
    int i = blockIdx.x * 256 + threadIdx.x;
    if (i < n4) {
        float4 v = ((const float4*)s)[i];
        v.x = to_tf32(v.x); v.y = to_tf32(v.y);
        v.z = to_tf32(v.z); v.w = to_tf32(v.w);
        ((float4*)d)[i] = v;
    }
}

// =============================== GEMM core ==================================
// C[M,N] = A[M,K] @ W[N,K]^T  (M=8192, N=K=2048), TF32 wmma m16n16k8.
// Inputs PRE-ROUNDED to tf32 in gmem: mainloop has ZERO cvt instructions.
// Block 128x128x32, 256 threads (8 warps 4x2, warp 32x64), cp.async 2-stage.
#define G_BM 128
#define G_BN 128
#define G_BK 32
#define G_LD 36
#define G_BUF (G_BM * G_LD)            // 4608 floats
#define G_SMEM_BYTES (4 * G_BUF * 4)   // 73728 B
#define G_NT (DIMM / G_BK)             // 64

#define GEMM_BODY(A_, W_)                                                      \
    extern __shared__ float dsm[];                                             \
    float* As[2] = { dsm,         dsm + 2 * G_BUF };                           \
    float* Bs[2] = { dsm + G_BUF, dsm + 3 * G_BUF };                           \
    const int bm = blockIdx.y * G_BM;                                          \
    const int bn = blockIdx.x * G_BN;                                          \
    const int tid = threadIdx.x;                                               \
    const int warp = tid >> 5;                                                 \
    const int wm = warp >> 1;                                                  \
    const int wn = warp & 1;                                                   \
    const int lr = tid >> 3;                                                   \
    const int lc = (tid & 7) << 2;                                             \
    wmma::fragment<wmma::accumulator, 16, 16, 8, float> acc[2][4];             \
    _Pragma("unroll")                                                          \
    for (int i = 0; i < 2; i++)                                                \
        _Pragma("unroll")                                                      \
        for (int j = 0; j < 4; j++) wmma::fill_fragment(acc[i][j], 0.0f);      \
    _Pragma("unroll")                                                          \
    for (int p = 0; p < 4; p++) {                                              \
        CP16(smem_u32(&As[0][(lr + p * 32) * G_LD + lc]),                      \
             &A_[(bm + lr + p * 32) * DIMM + lc]);                             \
        CP16(smem_u32(&Bs[0][(lr + p * 32) * G_LD + lc]),                      \
             &W_[(bn + lr + p * 32) * DIMM + lc]);                             \
    }                                                                          \
    CPC();                                                                     \
    for (int it = 0; it < G_NT; it++) {                                        \
        if (it + 1 < G_NT) {                                                   \
            const int nb = (it + 1) & 1;                                       \
            const int k0 = (it + 1) * G_BK;                                    \
            _Pragma("unroll")                                                  \
            for (int p = 0; p < 4; p++) {                                      \
                CP16(smem_u32(&As[nb][(lr + p * 32) * G_LD + lc]),             \
                     &A_[(bm + lr + p * 32) * DIMM + k0 + lc]);                \
                CP16(smem_u32(&Bs[nb][(lr + p * 32) * G_LD + lc]),             \
                     &W_[(bn + lr + p * 32) * DIMM + k0 + lc]);                \
            }                                                                  \
        }                                                                      \
        CPC(); CPW1(); __syncthreads();                                        \
        const float* Ac = As[it & 1];                                          \
        const float* Bc = Bs[it & 1];                                          \
        _Pragma("unroll")                                                      \
        for (int kk = 0; kk < G_BK; kk += 8) {                                 \
            wmma::fragment<wmma::matrix_a, 16, 16, 8, wmma::precision::tf32,   \
                           wmma::row_major> af[2];                             \
            wmma::fragment<wmma::matrix_b, 16, 16, 8, wmma::precision::tf32,   \
                           wmma::col_major> bf[4];                             \
            _Pragma("unroll")                                                  \
            for (int i = 0; i < 2; i++)                                        \
                wmma::load_matrix_sync(af[i],                                  \
                    &Ac[(wm * 32 + i * 16) * G_LD + kk], G_LD);                \
            _Pragma("unroll")                                                  \
            for (int j = 0; j < 4; j++)                                        \
                wmma::load_matrix_sync(bf[j],                                  \
                    &Bc[(wn * 64 + j * 16) * G_LD + kk], G_LD);                \
            _Pragma("unroll")                                                  \
            for (int i = 0; i < 2; i++)                                        \
                _Pragma("unroll")                                              \
                for (int j = 0; j < 4; j++)                                    \
                    wmma::mma_sync(acc[i][j], af[i], bf[j], acc[i][j]);        \
        }                                                                      \
        __syncthreads();                                                       \
    }

// ---- GEMM: roundedX @ roundedWv^T -> g_v (rounded, B,S,DIM) ----
__global__ __launch_bounds__(256, 2) void gemm_v() {
    const float* A = g_at;          // rounded X
    const float* W = g_w + 2 * WSZ; // rounded wv
    GEMM_BODY(A, W)
#pragma unroll
    for (int i = 0; i < 2; i++)
#pragma unroll
        for (int j = 0; j < 4; j++) {
#pragma unroll
            for (int e = 0; e < acc[i][j].num_elements; e++)
                acc[i][j].x[e] = to_tf32(acc[i][j].x[e]);
            wmma::store_matrix_sync(
                &g_v[(bm + wm * 32 + i * 16) * DIMM + bn + wn * 64 + j * 16],
                acc[i][j], DIMM, wmma::mem_row_major);
        }
}

// ---- GEMM: g_at(rounded attn) @ roundedWo^T -> out (fp32 final) ----
__global__ __launch_bounds__(256, 2) void gemm_out(float* __restrict__ C) {
    const float* A = g_at;
    const float* W = g_w + 3 * WSZ;
    GEMM_BODY(A, W)
#pragma unroll
    for (int i = 0; i < 2; i++)
#pragma unroll
        for (int j = 0; j < 4; j++)
            wmma::store_matrix_sync(
                &C[(bm + wm * 32 + i * 16) * DIMM + bn + wn * 64 + j * 16],
                acc[i][j], DIMM, wmma::mem_row_major);
}

// ---- fused GEMM + RMSNorm + RoPE + transpose for Q/K ----
#define C_LD 132

__global__ __launch_bounds__(256, 2) void gemm_qk(const float* __restrict__ nw,
                                                  const float* __restrict__ ct,
                                                  const float* __restrict__ st,
                                                  int which) {
    const float* A = g_at;                       // rounded X
    const float* W = g_w + (which ? WSZ : 0);    // rounded wq / wk
    GEMM_BODY(A, W)

    // Mainloop ends with __syncthreads(): safe to overwrite buffers with C.
    float* Cs = dsm;               // 128*132 = 16896 floats <= 18432 avail
#pragma unroll
    for (int i = 0; i < 2; i++)
#pragma unroll
        for (int j = 0; j < 4; j++)
            wmma::store_matrix_sync(&Cs[(wm * 32 + i * 16) * C_LD + wn * 64 + j * 16],
                                    acc[i][j], C_LD, wmma::mem_row_major);
    __syncthreads();

    const int lane = tid & 31;
    const int h = bn >> 7;
    const float4 wv4 = ((const float4*)nw)[lane];
    const float sgn = (lane < 16) ? -1.0f : 1.0f;
    float* dstT = which ? g_kt : g_qt;

#pragma unroll
    for (int i = 0; i < 16; i++) {
        const int r = warp + 8 * i;            // 0..127
        float4 v = *(const float4*)&Cs[r * C_LD + lane * 4];
        float ssum = v.x * v.x + v.y * v.y + v.z * v.z + v.w * v.w;
#pragma unroll
        for (int o = 16; o; o >>= 1) ssum += __shfl_xor_sync(0xffffffffu, ssum, o);
        const float rinv = rsqrtf(ssum * (1.0f / HDD) + 1e-6f);

        float n0 = v.x * rinv * wv4.x;
        float n1 = v.y * rinv * wv4.y;
        float n2 = v.z * rinv * wv4.z;
        float n3 = v.w * rinv * wv4.w;

        float o0 = __shfl_xor_sync(0xffffffffu, n0, 16);
        float o1 = __shfl_xor_sync(0xffffffffu, n1, 16);
        float o2 = __shfl_xor_sync(0xffffffffu, n2, 16);
        float o3 = __shfl_xor_sync(0xffffffffu, n3, 16);

        const int m = bm + r;
        const int b = m >> 11;
        const int s = m & (SS - 1);

        const float4 c4 = ((const float4*)(ct + s * HDD))[lane];
        const float4 s4 = ((const float4*)(st + s * HDD))[lane];
        float4 outv;
        outv.x = to_tf32(n0 * c4.x + sgn * o0 * s4.x);
        outv.y = to_tf32(n1 * c4.y + sgn * o1 * s4.y);
        outv.z = to_tf32(n2 * c4.z + sgn * o2 * s4.z);
        outv.w = to_tf32(n3 * c4.w + sgn * o3 * s4.w);

        ((float4*)&dstT[((b * HH + h) * SS + s) * HDD])[lane] = outv;
    }
}

// ============================ Flash attention ===============================
// All gmem inputs pre-rounded tf32: no cvt in gathers. Only P rounds post-exp.
#define F_QT 128
#define F_KT 32
#define F_LQ 132
#define F_LK 132
#define F_LV 136
#define F_LP 36
#define F_KBUF (F_KT * F_LK)                  // 4224
#define F_VBUF (F_KT * F_LV)                  // 4352
#define F_OFF_K (F_QT * F_LQ)                 // 16896
#define F_OFF_V (F_OFF_K + 2 * F_KBUF)        // 25344
#define F_OFF_P (F_OFF_V + 2 * F_VBUF)        // 34048
#define F_SM_FLOATS (F_OFF_P + 8 * 16 * F_LP) // 38656 -> 154624 B

#define MMA_TF32(Cr, a0, a1, a2, a3, b0, b1)                                  \
    asm volatile("mma.sync.aligned.m16n8k8.row.col.f32.tf32.tf32.f32 "        \
                 "{%0,%1,%2,%3}, {%4,%5,%6,%7}, {%8,%9}, {%0,%1,%2,%3};"      \
                 : "+f"(Cr[0]), "+f"(Cr[1]), "+f"(Cr[2]), "+f"(Cr[3])         \
                 : "r"(a0), "r"(a1), "r"(a2), "r"(a3), "r"(b0), "r"(b1))

__global__ __launch_bounds__(256, 1) void flash_attn() {
    extern __shared__ float sm[];
    float* qs = sm;
    float* kbuf[2] = { sm + F_OFF_K, sm + F_OFF_K + F_KBUF };
    float* vbuf[2] = { sm + F_OFF_V, sm + F_OFF_V + F_VBUF };

    const int tid = threadIdx.x;
    const int w = tid >> 5;
    const int lane = tid & 31;
    const int g = lane >> 2;
    const int q = lane & 3;
    const int bh = blockIdx.y;
    const int b = bh >> 4, h = bh & 15;
    const int qt0 = blockIdx.x * F_QT;
    float* pw = sm + F_OFF_P + w * 16 * F_LP;

    // ---- Q tile (128x128) to smem (already rounded) ----
    const float* qbase = g_qt + (bh * SS + qt0) * HDD;
#pragma unroll
    for (int p = 0; p < 16; p++) {
        int idx = tid + p * 256;
        int r = idx >> 5, c4 = (idx & 31) << 2;
        *(float4*)&qs[r * F_LQ + c4] = *(const float4*)&qbase[r * HDD + c4];
    }

    float o[16][4];
#pragma unroll
    for (int nt = 0; nt < 16; nt++)
#pragma unroll
        for (int e = 0; e < 4; e++) o[nt][e] = 0.0f;
    float m0 = BIGNEG, m1 = BIGNEG, l0 = 0.0f, l1 = 0.0f;

    const int row0g = qt0 + w * 16 + g;
    const int row1g = row0g + 8;
    const int nj = 4 * blockIdx.x + 4;

    {
        const float* kg = g_kt + (bh * SS) * HDD;
        const float* vg = g_v + (b * SS) * DIMM + h * HDD;
#pragma unroll
        for (int p = 0; p < 4; p++) {
            int idx = tid + p * 256;
            int r = idx >> 5, c4 = (idx & 31) << 2;
            CP16(smem_u32(&kbuf[0][r * F_LK + c4]), &kg[r * HDD + c4]);
            CP16(smem_u32(&vbuf[0][r * F_LV + c4]), &vg[r * DIMM + c4]);
        }
    }
    CPC();

    for (int j = 0; j < nj; j++) {
        if (j + 1 < nj) {
            const int nb = (j + 1) & 1;
            const float* kg = g_kt + (bh * SS + (j + 1) * F_KT) * HDD;
            const float* vg = g_v + (b * SS + (j + 1) * F_KT) * DIMM + h * HDD;
#pragma unroll
            for (int p = 0; p < 4; p++) {
                int idx = tid + p * 256;
                int r = idx >> 5, c4 = (idx & 31) << 2;
                CP16(smem_u32(&kbuf[nb][r * F_LK + c4]), &kg[r * HDD + c4]);
                CP16(smem_u32(&vbuf[nb][r * F_LV + c4]), &vg[r * DIMM + c4]);
            }
        }
        CPC(); CPW1(); __syncthreads();
        const float* ks = kbuf[j & 1];
        const float* vs = vbuf[j & 1];

        // ---- S = Q @ K^T : 16 x 32 per warp ----
        float c[4][4];
#pragma unroll
        for (int nt = 0; nt < 4; nt++)
#pragma unroll
            for (int e = 0; e < 4; e++) c[nt][e] = 0.0f;
#pragma unroll
        for (int ks8 = 0; ks8 < 16; ks8++) {
            const int kk = ks8 * 8;
            uint32_t a0 = __float_as_uint(qs[(w * 16 + g)     * F_LQ + kk + q]);
            uint32_t a1 = __float_as_uint(qs[(w * 16 + g + 8) * F_LQ + kk + q]);
            uint32_t a2 = __float_as_uint(qs[(w * 16 + g)     * F_LQ + kk + q + 4]);
            uint32_t a3 = __float_as_uint(qs[(w * 16 + g + 8) * F_LQ + kk + q + 4]);
#pragma unroll
            for (int nt = 0; nt < 4; nt++) {
                uint32_t b0 = __float_as_uint(ks[(nt * 8 + g) * F_LK + kk + q]);
                uint32_t b1 = __float_as_uint(ks[(nt * 8 + g) * F_LK + kk + q + 4]);
                MMA_TF32(c[nt], a0, a1, a2, a3, b0, b1);
            }
        }

        // ---- online softmax ----
        float mx0 = BIGNEG, mx1 = BIGNEG;
        if (j >= 4 * blockIdx.x) {    // diagonal tiles: causal mask
#pragma unroll
            for (int nt = 0; nt < 4; nt++) {
                const int cb = j * F_KT + nt * 8 + q * 2;
                c[nt][0] = (cb     <= row0g) ? c[nt][0] * SCALE : BIGNEG;
                c[nt][1] = (cb + 1 <= row0g) ? c[nt][1] * SCALE : BIGNEG;
                c[nt][2] = (cb     <= row1g) ? c[nt][2] * SCALE : BIGNEG;
                c[nt][3] = (cb + 1 <= row1g) ? c[nt][3] * SCALE : BIGNEG;
                mx0 = fmaxf(mx0, fmaxf(c[nt][0], c[nt][1]));
                mx1 = fmaxf(mx1, fmaxf(c[nt][2], c[nt][3]));
            }
        } else {
#pragma unroll
            for (int nt = 0; nt < 4; nt++) {
                c[nt][0] *= SCALE; c[nt][1] *= SCALE;
                c[nt][2] *= SCALE; c[nt][3] *= SCALE;
                mx0 = fmaxf(mx0, fmaxf(c[nt][0], c[nt][1]));
                mx1 = fmaxf(mx1, fmaxf(c[nt][2], c[nt][3]));
            }
        }
        mx0 = fmaxf(mx0, __shfl_xor_sync(0xffffffffu, mx0, 1));
        mx0 = fmaxf(mx0, __shfl_xor_sync(0xffffffffu, mx0, 2));
        mx1 = fmaxf(mx1, __shfl_xor_sync(0xffffffffu, mx1, 1));
        mx1 = fmaxf(mx1, __shfl_xor_sync(0xffffffffu, mx1, 2));

        const float mn0 = fmaxf(m0, mx0), mn1 = fmaxf(m1, mx1);
        const float al0 = __expf(m0 - mn0), al1 = __expf(m1 - mn1);
        float sum0 = 0.0f, sum1 = 0.0f;
#pragma unroll
        for (int nt = 0; nt < 4; nt++) {
            c[nt][0] = __expf(c[nt][0] - mn0); sum0 += c[nt][0];
            c[nt][1] = __expf(c[nt][1] - mn0); sum0 += c[nt][1];
            c[nt][2] = __expf(c[nt][2] - mn1); sum1 += c[nt][2];
            c[nt][3] = __expf(c[nt][3] - mn1); sum1 += c[nt][3];
        }
        sum0 += __shfl_xor_sync(0xffffffffu, sum0, 1);
        sum0 += __shfl_xor_sync(0xffffffffu, sum0, 2);
        sum1 += __shfl_xor_sync(0xffffffffu, sum1, 1);
        sum1 += __shfl_xor_sync(0xffffffffu, sum1, 2);
        l0 = l0 * al0 + sum0;
        l1 = l1 * al1 + sum1;
        m0 = mn0; m1 = mn1;
#pragma unroll
        for (int nt = 0; nt < 16; nt++) {
            o[nt][0] *= al0; o[nt][1] *= al0;
            o[nt][2] *= al1; o[nt][3] *= al1;
        }

        // ---- write P (16x32) rounded to smem ----
#pragma unroll
        for (int nt = 0; nt < 4; nt++) {
            pw[g       * F_LP + nt * 8 + q * 2 + 0] = to_tf32(c[nt][0]);
            pw[g       * F_LP + nt * 8 + q * 2 + 1] = to_tf32(c[nt][1]);
            pw[(g + 8) * F_LP + nt * 8 + q * 2 + 0] = to_tf32(c[nt][2]);
            pw[(g + 8) * F_LP + nt * 8 + q * 2 + 1] = to_tf32(c[nt][3]);
        }
        __syncwarp();

        // ---- O += P @ V : 16 x 128 per warp ----
#pragma unroll
        for (int ks8 = 0; ks8 < 4; ks8++) {
            const int kk = ks8 * 8;
            uint32_t a0 = __float_as_uint(pw[g       * F_LP + kk + q]);
            uint32_t a1 = __float_as_uint(pw[(g + 8) * F_LP + kk + q]);
            uint32_t a2 = __float_as_uint(pw[g       * F_LP + kk + q + 4]);
            uint32_t a3 = __float_as_uint(pw[(g + 8) * F_LP + kk + q + 4]);
#pragma unroll
            for (int nt = 0; nt < 16; nt++) {
                uint32_t b0 = __float_as_uint(vs[(kk + q)     * F_LV + nt * 8 + g]);
                uint32_t b1 = __float_as_uint(vs[(kk + q + 4) * F_LV + nt * 8 + g]);
                MMA_TF32(o[nt], a0, a1, a2, a3, b0, b1);
            }
        }
        __syncthreads();
    }

    // ---- epilogue: rounded O / l -> g_at (B,S,DIM) for the output GEMM ----
    const float inv0 = 1.0f / l0, inv1 = 1.0f / l1;
    float* ob0 = g_at + (b * SS + row0g) * DIMM + h * HDD;
    float* ob1 = g_at + (b * SS + row1g) * DIMM + h * HDD;
#pragma unroll
    for (int nt = 0; nt < 16; nt++) {
        const int d = nt * 8 + q * 2;
        *(float2*)&ob0[d] = make_float2(to_tf32(o[nt][0] * inv0),
                                        to_tf32(o[nt][1] * inv0));
        *(float2*)&ob1[d] = make_float2(to_tf32(o[nt][2] * inv1),
                                        to_tf32(o[nt][3] * inv1));
    }
}

// =============================== launch =====================================
extern "C" void kernel_launch(void* const* d_in, const int* in_sizes, int n_in,
                              void* d_out, int out_size) {
    (void)in_sizes; (void)n_in; (void)out_size;
    const float* x  = (const float*)d_in[0];
    const float* ct = (const float*)d_in[1];
    const float* st = (const float*)d_in[2];
    // d_in[3] = causal mask — implemented analytically
    const float* wq = (const float*)d_in[4];
    const float* wk = (const float*)d_in[5];
    const float* wv = (const float*)d_in[6];
    const float* wo = (const float*)d_in[7];
    const float* qw = (const float*)d_in[8];
    const float* kw = (const float*)d_in[9];
    float* out = (float*)d_out;

    cudaFuncSetAttribute(gemm_qk,  cudaFuncAttributeMaxDynamicSharedMemorySize, G_SMEM_BYTES);
    cudaFuncSetAttribute(gemm_v,   cudaFuncAttributeMaxDynamicSharedMemorySize, G_SMEM_BYTES);
    cudaFuncSetAttribute(gemm_out, cudaFuncAttributeMaxDynamicSharedMemorySize, G_SMEM_BYTES);
    cudaFuncSetAttribute(flash_attn, cudaFuncAttributeMaxDynamicSharedMemorySize,
                         F_SM_FLOATS * (int)sizeof(float));

    float* gat;  cudaGetSymbolAddress((void**)&gat, g_at);  // device ptr for prepass dst
    float* gw;   cudaGetSymbolAddress((void**)&gw,  g_w);

    // ---- prepass: round X and all weights to tf32 in scratch ----
    round_copy<<<(MM * DIMM / 4) / 256, 256>>>(x,  gat,          MM * DIMM / 4);
    round_copy<<<(WSZ / 4) / 256, 256>>>(wq, gw + 0 * WSZ, WSZ / 4);
    round_copy<<<(WSZ / 4) / 256, 256>>>(wk, gw + 1 * WSZ, WSZ / 4);
    round_copy<<<(WSZ / 4) / 256, 256>>>(wv, gw + 2 * WSZ, WSZ / 4);
    round_copy<<<(WSZ / 4) / 256, 256>>>(wo, gw + 3 * WSZ, WSZ / 4);

    const dim3 gGrid(DIMM / G_BN, MM / G_BM);   // (16, 64)

    gemm_qk<<<gGrid, 256, G_SMEM_BYTES>>>(qw, ct, st, 0);
    gemm_qk<<<gGrid, 256, G_SMEM_BYTES>>>(kw, ct, st, 1);
    gemm_v <<<gGrid, 256, G_SMEM_BYTES>>>();

    flash_attn<<<dim3(SS / F_QT, BB * HH), 256, F_SM_FLOATS * sizeof(float)>>>();

    gemm_out<<<gGrid, 256, G_SMEM_BYTES>>>(out);
}

// round 14
// speedup vs baseline: 3.0227x; 2.8290x over previous
#include <cuda_runtime.h>
#include <cuda_fp16.h>
#include <mma.h>
#include <cstdint>

using namespace nvcuda;

// Problem constants
#define BB   4
#define SS   2048
#define DIMM 2048
#define HH   16
#define HDD  128
#define MM   (BB*SS)            // 8192
#define WSZ  (DIMM*DIMM)        // 4194304
#define SCALE 0.08838834764831845f   // 1/sqrt(128)
#define BIGNEG (-1e30f)

// ---------------- scratch (__device__ globals: allocation-free) -------------
__device__ __half g_qt [MM*DIMM];   // Q normed+roped (fp16), (B,H,S,HD)
__device__ __half g_kt [MM*DIMM];   // K normed+roped (fp16), (B,H,S,HD)
__device__ __half g_v  [MM*DIMM];   // V projection   (fp16), (B,S,DIM)
__device__ __half g_at [MM*DIMM];   // phase 1: fp16 X; phase 2: attn out (fp16)
__device__ __half g_w  [4*WSZ];     // fp16 wq,wk,wv,wo

__device__ __forceinline__ uint32_t smem_u32(const void* p) {
    return (uint32_t)__cvta_generic_to_shared(p);
}
#define CP16(dst, src) asm volatile("cp.async.cg.shared.global [%0], [%1], 16;" \
                                    :: "r"(dst), "l"(src))
#define CPC()  asm volatile("cp.async.commit_group;")
#define CPW1() asm volatile("cp.async.wait_group 1;")

// ---------------- prepass: fp32 -> fp16 rounding copy ------------------------
__global__ __launch_bounds__(256) void round_copy_h(const float* __restrict__ s,
                                                    __half* __restrict__ d, int n8) {
    int i = blockIdx.x * 256 + threadIdx.x;
    if (i < n8) {
        float4 a = ((const float4*)s)[2 * i];
        float4 b = ((const float4*)s)[2 * i + 1];
        __half2 h0 = __floats2half2_rn(a.x, a.y);
        __half2 h1 = __floats2half2_rn(a.z, a.w);
        __half2 h2 = __floats2half2_rn(b.x, b.y);
        __half2 h3 = __floats2half2_rn(b.z, b.w);
        uint4 o;
        o.x = *(uint32_t*)&h0; o.y = *(uint32_t*)&h1;
        o.z = *(uint32_t*)&h2; o.w = *(uint32_t*)&h3;
        ((uint4*)d)[i] = o;
    }
}

// =============================== GEMM core ==================================
// C[M,N] = A[M,K] @ W[N,K]^T  (M=8192, N=K=2048), fp16 wmma m16n16k16, fp32 acc.
// Block 128x128x64, 256 threads (8 warps 4x2, warp 32x64), cp.async 2-stage.
#define G_BM 128
#define G_BN 128
#define G_BK 64
#define G_LD 72                        // halves; 144B row stride (same as tf32 ver)
#define G_BUF (G_BM * G_LD)            // 9216 halves = 18432 B per tile buffer
#define G_SMEM_BYTES (4 * G_BUF * 2)   // 73728 B
#define G_NT (DIMM / G_BK)             // 32

#define GEMM_BODY(A_, W_)                                                      \
    extern __shared__ __half dsm[];                                            \
    __half* As[2] = { dsm,         dsm + 2 * G_BUF };                          \
    __half* Bs[2] = { dsm + G_BUF, dsm + 3 * G_BUF };                          \
    const int bm = blockIdx.y * G_BM;                                          \
    const int bn = blockIdx.x * G_BN;                                          \
    const int tid = threadIdx.x;                                               \
    const int warp = tid >> 5;                                                 \
    const int wm = warp >> 1;                                                  \
    const int wn = warp & 1;                                                   \
    const int lr = tid >> 3;                                                   \
    const int lc = (tid & 7) << 3;                                             \
    wmma::fragment<wmma::accumulator, 16, 16, 16, float> acc[2][4];            \
    _Pragma("unroll")                                                          \
    for (int i = 0; i < 2; i++)                                                \
        _Pragma("unroll")                                                      \
        for (int j = 0; j < 4; j++) wmma::fill_fragment(acc[i][j], 0.0f);      \
    _Pragma("unroll")                                                          \
    for (int p = 0; p < 4; p++) {                                              \
        CP16(smem_u32(&As[0][(lr + p * 32) * G_LD + lc]),                      \
             &A_[(bm + lr + p * 32) * DIMM + lc]);                             \
        CP16(smem_u32(&Bs[0][(lr + p * 32) * G_LD + lc]),                      \
             &W_[(bn + lr + p * 32) * DIMM + lc]);                             \
    }                                                                          \
    CPC();                                                                     \
    for (int it = 0; it < G_NT; it++) {                                        \
        if (it + 1 < G_NT) {                                                   \
            const int nb = (it + 1) & 1;                                       \
            const int k0 = (it + 1) * G_BK;                                    \
            _Pragma("unroll")                                                  \
            for (int p = 0; p < 4; p++) {                                      \
                CP16(smem_u32(&As[nb][(lr + p * 32) * G_LD + lc]),             \
                     &A_[(bm + lr + p * 32) * DIMM + k0 + lc]);                \
                CP16(smem_u32(&Bs[nb][(lr + p * 32) * G_LD + lc]),             \
                     &W_[(bn + lr + p * 32) * DIMM + k0 + lc]);                \
            }                                                                  \
        }                                                                      \
        CPC(); CPW1(); __syncthreads();                                        \
        const __half* Ac = As[it & 1];                                         \
        const __half* Bc = Bs[it & 1];                                         \
        _Pragma("unroll")                                                      \
        for (int kk = 0; kk < G_BK; kk += 16) {                                \
            wmma::fragment<wmma::matrix_a, 16, 16, 16, __half,                 \
                           wmma::row_major> af[2];                             \
            wmma::fragment<wmma::matrix_b, 16, 16, 16, __half,                 \
                           wmma::col_major> bf[4];                             \
            _Pragma("unroll")                                                  \
            for (int i = 0; i < 2; i++)                                        \
                wmma::load_matrix_sync(af[i],                                  \
                    &Ac[(wm * 32 + i * 16) * G_LD + kk], G_LD);                \
            _Pragma("unroll")                                                  \
            for (int j = 0; j < 4; j++)                                        \
                wmma::load_matrix_sync(bf[j],                                  \
                    &Bc[(wn * 64 + j * 16) * G_LD + kk], G_LD);                \
            _Pragma("unroll")                                                  \
            for (int i = 0; i < 2; i++)                                        \
                _Pragma("unroll")                                              \
                for (int j = 0; j < 4; j++)                                    \
                    wmma::mma_sync(acc[i][j], af[i], bf[j], acc[i][j]);        \
        }                                                                      \
        __syncthreads();                                                       \
    }

#define C_LD 132   // float C-tile ld in smem

// ---- GEMM: X(h) @ Wv(h)^T -> g_v (fp16, B,S,DIM) ----
__global__ __launch_bounds__(256, 2) void gemm_v() {
    const __half* A = g_at;          // fp16 X
    const __half* W = g_w + 2 * WSZ; // fp16 wv
    GEMM_BODY(A, W)
    float* Cs = (float*)dsm;         // 67584 B <= 73728 B
#pragma unroll
    for (int i = 0; i < 2; i++)
#pragma unroll
        for (int j = 0; j < 4; j++)
            wmma::store_matrix_sync(&Cs[(wm * 32 + i * 16) * C_LD + wn * 64 + j * 16],
                                    acc[i][j], C_LD, wmma::mem_row_major);
    __syncthreads();
    const int lane = tid & 31;
#pragma unroll
    for (int i = 0; i < 16; i++) {
        const int r = warp + 8 * i;
        float4 v = *(const float4*)&Cs[r * C_LD + lane * 4];
        __half2 h01 = __floats2half2_rn(v.x, v.y);
        __half2 h23 = __floats2half2_rn(v.z, v.w);
        uint2 o; o.x = *(uint32_t*)&h01; o.y = *(uint32_t*)&h23;
        *(uint2*)&g_v[(bm + r) * DIMM + bn + lane * 4] = o;
    }
}

// ---- GEMM: g_at(attn fp16) @ Wo(h)^T -> out (fp32 final) ----
__global__ __launch_bounds__(256, 2) void gemm_out(float* __restrict__ C) {
    const __half* A = g_at;
    const __half* W = g_w + 3 * WSZ;
    GEMM_BODY(A, W)
#pragma unroll
    for (int i = 0; i < 2; i++)
#pragma unroll
        for (int j = 0; j < 4; j++)
            wmma::store_matrix_sync(
                &C[(bm + wm * 32 + i * 16) * DIMM + bn + wn * 64 + j * 16],
                acc[i][j], DIMM, wmma::mem_row_major);
}

// ---- fused GEMM + RMSNorm + RoPE + transpose for Q/K (fp16 out) ----
__global__ __launch_bounds__(256, 2) void gemm_qk(const float* __restrict__ nw,
                                                  const float* __restrict__ ct,
                                                  const float* __restrict__ st,
                                                  int which) {
    const __half* A = g_at;                      // fp16 X
    const __half* W = g_w + (which ? WSZ : 0);   // fp16 wq / wk
    GEMM_BODY(A, W)

    float* Cs = (float*)dsm;
#pragma unroll
    for (int i = 0; i < 2; i++)
#pragma unroll
        for (int j = 0; j < 4; j++)
            wmma::store_matrix_sync(&Cs[(wm * 32 + i * 16) * C_LD + wn * 64 + j * 16],
                                    acc[i][j], C_LD, wmma::mem_row_major);
    __syncthreads();

    const int lane = tid & 31;
    const int h = bn >> 7;
    const float4 wv4 = ((const float4*)nw)[lane];
    const float sgn = (lane < 16) ? -1.0f : 1.0f;
    __half* dstT = which ? g_kt : g_qt;

#pragma unroll
    for (int i = 0; i < 16; i++) {
        const int r = warp + 8 * i;            // 0..127
        float4 v = *(const float4*)&Cs[r * C_LD + lane * 4];
        float ssum = v.x * v.x + v.y * v.y + v.z * v.z + v.w * v.w;
#pragma unroll
        for (int o = 16; o; o >>= 1) ssum += __shfl_xor_sync(0xffffffffu, ssum, o);
        const float rinv = rsqrtf(ssum * (1.0f / HDD) + 1e-6f);

        float n0 = v.x * rinv * wv4.x;
        float n1 = v.y * rinv * wv4.y;
        float n2 = v.z * rinv * wv4.z;
        float n3 = v.w * rinv * wv4.w;

        float o0 = __shfl_xor_sync(0xffffffffu, n0, 16);
        float o1 = __shfl_xor_sync(0xffffffffu, n1, 16);
        float o2 = __shfl_xor_sync(0xffffffffu, n2, 16);
        float o3 = __shfl_xor_sync(0xffffffffu, n3, 16);

        const int m = bm + r;
        const int b = m >> 11;
        const int s = m & (SS - 1);

        const float4 c4 = ((const float4*)(ct + s * HDD))[lane];
        const float4 s4 = ((const float4*)(st + s * HDD))[lane];
        __half2 h01 = __floats2half2_rn(n0 * c4.x + sgn * o0 * s4.x,
                                        n1 * c4.y + sgn * o1 * s4.y);
        __half2 h23 = __floats2half2_rn(n2 * c4.z + sgn * o2 * s4.z,
                                        n3 * c4.w + sgn * o3 * s4.w);
        uint2 o; o.x = *(uint32_t*)&h01; o.y = *(uint32_t*)&h23;
        *(uint2*)&dstT[((b * HH + h) * SS + s) * HDD + lane * 4] = o;
    }
}

// ============================ Flash attention ===============================
// fp16 mma.m16n8k16 for S=QK^T and O+=P@V; fp32 softmax/accumulators.
// Block = (b,h) x 128 query rows, 8 warps (16 rows each), KV tiles of 32.
// K double-buffered via cp.async; V LDG->register->transposed STS.
#define F_QT 128
#define F_KT 32
#define F_LQ 136                       // halves
#define F_LK 136
#define F_LVT 38                       // v^T ld (halves)
#define F_LP 40                        // per-warp P ld (halves)
#define F_KBUF (F_KT * F_LK)                   // 4352 halves
#define F_VBUF (HDD * F_LVT)                   // 4864 halves
#define F_OFF_K (F_QT * F_LQ)                  // 17408
#define F_OFF_V (F_OFF_K + 2 * F_KBUF)         // 26112
#define F_OFF_P (F_OFF_V + 2 * F_VBUF)         // 35840
#define F_SM_HALVES (F_OFF_P + 8 * 16 * F_LP)  // 40960 -> 81920 B

#define MMA_F16(Cr, a0, a1, a2, a3, b0, b1)                                   \
    asm volatile("mma.sync.aligned.m16n8k16.row.col.f32.f16.f16.f32 "         \
                 "{%0,%1,%2,%3}, {%4,%5,%6,%7}, {%8,%9}, {%0,%1,%2,%3};"      \
                 : "+f"(Cr[0]), "+f"(Cr[1]), "+f"(Cr[2]), "+f"(Cr[3])         \
                 : "r"(a0), "r"(a1), "r"(a2), "r"(a3), "r"(b0), "r"(b1))

__device__ __forceinline__ void sts_v_transposed(__half* vt, uint4 v0, uint4 v1,
                                                 int tid) {
#pragma unroll
    for (int p = 0; p < 2; p++) {
        const uint4 v = p ? v1 : v0;
        const int idx = tid + p * 256;
        const int r = idx >> 4;              // kv 0..31
        const int c8 = (idx & 15) << 3;      // d base 0..120
        uint32_t parts[4] = { v.x, v.y, v.z, v.w };
#pragma unroll
        for (int k = 0; k < 4; k++) {
            __half2 hp = *(__half2*)&parts[k];
            vt[(c8 + 2 * k)     * F_LVT + r] = __low2half(hp);
            vt[(c8 + 2 * k + 1) * F_LVT + r] = __high2half(hp);
        }
    }
}

__global__ __launch_bounds__(256, 1) void flash_attn() {
    extern __shared__ __half fsm[];
    __half* qs = fsm;
    __half* kbuf[2] = { fsm + F_OFF_K, fsm + F_OFF_K + F_KBUF };
    __half* vbuf[2] = { fsm + F_OFF_V, fsm + F_OFF_V + F_VBUF };

    const int tid = threadIdx.x;
    const int w = tid >> 5;
    const int lane = tid & 31;
    const int g = lane >> 2;     // 0..7
    const int q = lane & 3;      // 0..3
    const int bh = blockIdx.y;
    const int b = bh >> 4, h = bh & 15;
    const int qt0 = blockIdx.x * F_QT;
    __half* pw = fsm + F_OFF_P + w * 16 * F_LP;

    const __half* kgb = g_kt + (bh * SS) * HDD;
    const __half* vgb = g_v + (b * SS) * DIMM + h * HDD;

    // ---- prologue: cp K(0); LDG V(0); plain-load Q; STS V(0) ----
    {
#pragma unroll
        for (int p = 0; p < 2; p++) {
            int idx = tid + p * 256;
            int r = idx >> 4, c8 = (idx & 15) << 3;
            CP16(smem_u32(&kbuf[0][r * F_LK + c8]), &kgb[r * HDD + c8]);
        }
        CPC();
        uint4 v0, v1;
        {
            int idx0 = tid, idx1 = tid + 256;
            v0 = *(const uint4*)&vgb[(idx0 >> 4) * DIMM + ((idx0 & 15) << 3)];
            v1 = *(const uint4*)&vgb[(idx1 >> 4) * DIMM + ((idx1 & 15) << 3)];
        }
        const __half* qbase = g_qt + (bh * SS + qt0) * HDD;
#pragma unroll
        for (int p = 0; p < 8; p++) {
            int idx = tid + p * 256;
            int r = idx >> 4, c8 = (idx & 15) << 3;
            *(uint4*)&qs[r * F_LQ + c8] = *(const uint4*)&qbase[r * HDD + c8];
        }
        sts_v_transposed(vbuf[0], v0, v1, tid);
    }

    float o[16][4];
#pragma unroll
    for (int nt = 0; nt < 16; nt++)
#pragma unroll
        for (int e = 0; e < 4; e++) o[nt][e] = 0.0f;
    float m0 = BIGNEG, m1 = BIGNEG, l0 = 0.0f, l1 = 0.0f;

    const int row0g = qt0 + w * 16 + g;
    const int row1g = row0g + 8;
    const int nj = 4 * blockIdx.x + 4;

    for (int j = 0; j < nj; j++) {
        uint4 nv0, nv1;
        const bool pf = (j + 1 < nj);
        if (pf) {
            const __half* kg = kgb + (j + 1) * F_KT * HDD;
            const __half* vg = vgb + (j + 1) * F_KT * DIMM;
#pragma unroll
            for (int p = 0; p < 2; p++) {
                int idx = tid + p * 256;
                int r = idx >> 4, c8 = (idx & 15) << 3;
                CP16(smem_u32(&kbuf[(j + 1) & 1][r * F_LK + c8]), &kg[r * HDD + c8]);
            }
            int idx0 = tid, idx1 = tid + 256;
            nv0 = *(const uint4*)&vg[(idx0 >> 4) * DIMM + ((idx0 & 15) << 3)];
            nv1 = *(const uint4*)&vg[(idx1 >> 4) * DIMM + ((idx1 & 15) << 3)];
        }
        CPC(); CPW1(); __syncthreads();
        const __half* ks = kbuf[j & 1];
        const __half* vs = vbuf[j & 1];

        // ---- S = Q @ K^T : 16 x 32 per warp (8 k-steps of 16) ----
        float c[4][4];
#pragma unroll
        for (int nt = 0; nt < 4; nt++)
#pragma unroll
            for (int e = 0; e < 4; e++) c[nt][e] = 0.0f;
#pragma unroll
        for (int ks16 = 0; ks16 < 8; ks16++) {
            const int kk = ks16 * 16;
            uint32_t a0 = *(const uint32_t*)&qs[(w * 16 + g)     * F_LQ + kk + 2 * q];
            uint32_t a1 = *(const uint32_t*)&qs[(w * 16 + g + 8) * F_LQ + kk + 2 * q];
            uint32_t a2 = *(const uint32_t*)&qs[(w * 16 + g)     * F_LQ + kk + 2 * q + 8];
            uint32_t a3 = *(const uint32_t*)&qs[(w * 16 + g + 8) * F_LQ + kk + 2 * q + 8];
#pragma unroll
            for (int nt = 0; nt < 4; nt++) {
                uint32_t b0 = *(const uint32_t*)&ks[(nt * 8 + g) * F_LK + kk + 2 * q];
                uint32_t b1 = *(const uint32_t*)&ks[(nt * 8 + g) * F_LK + kk + 2 * q + 8];
                MMA_F16(c[nt], a0, a1, a2, a3, b0, b1);
            }
        }

        // ---- online softmax ----
        float mx0 = BIGNEG, mx1 = BIGNEG;
        if (j >= 4 * blockIdx.x) {    // diagonal tiles: causal mask
#pragma unroll
            for (int nt = 0; nt < 4; nt++) {
                const int cb = j * F_KT + nt * 8 + q * 2;
                c[nt][0] = (cb     <= row0g) ? c[nt][0] * SCALE : BIGNEG;
                c[nt][1] = (cb + 1 <= row0g) ? c[nt][1] * SCALE : BIGNEG;
                c[nt][2] = (cb     <= row1g) ? c[nt][2] * SCALE : BIGNEG;
                c[nt][3] = (cb + 1 <= row1g) ? c[nt][3] * SCALE : BIGNEG;
                mx0 = fmaxf(mx0, fmaxf(c[nt][0], c[nt][1]));
                mx1 = fmaxf(mx1, fmaxf(c[nt][2], c[nt][3]));
            }
        } else {
#pragma unroll
            for (int nt = 0; nt < 4; nt++) {
                c[nt][0] *= SCALE; c[nt][1] *= SCALE;
                c[nt][2] *= SCALE; c[nt][3] *= SCALE;
                mx0 = fmaxf(mx0, fmaxf(c[nt][0], c[nt][1]));
                mx1 = fmaxf(mx1, fmaxf(c[nt][2], c[nt][3]));
            }
        }
        mx0 = fmaxf(mx0, __shfl_xor_sync(0xffffffffu, mx0, 1));
        mx0 = fmaxf(mx0, __shfl_xor_sync(0xffffffffu, mx0, 2));
        mx1 = fmaxf(mx1, __shfl_xor_sync(0xffffffffu, mx1, 1));
        mx1 = fmaxf(mx1, __shfl_xor_sync(0xffffffffu, mx1, 2));

        const float mn0 = fmaxf(m0, mx0), mn1 = fmaxf(m1, mx1);
        const float al0 = __expf(m0 - mn0), al1 = __expf(m1 - mn1);
        float sum0 = 0.0f, sum1 = 0.0f;
#pragma unroll
        for (int nt = 0; nt < 4; nt++) {
            c[nt][0] = __expf(c[nt][0] - mn0); sum0 += c[nt][0];
            c[nt][1] = __expf(c[nt][1] - mn0); sum0 += c[nt][1];
            c[nt][2] = __expf(c[nt][2] - mn1); sum1 += c[nt][2];
            c[nt][3] = __expf(c[nt][3] - mn1); sum1 += c[nt][3];
        }
        sum0 += __shfl_xor_sync(0xffffffffu, sum0, 1);
        sum0 += __shfl_xor_sync(0xffffffffu, sum0, 2);
        sum1 += __shfl_xor_sync(0xffffffffu, sum1, 1);
        sum1 += __shfl_xor_sync(0xffffffffu, sum1, 2);
        l0 = l0 * al0 + sum0;
        l1 = l1 * al1 + sum1;
        m0 = mn0; m1 = mn1;
#pragma unroll
        for (int nt = 0; nt < 16; nt++) {
            o[nt][0] *= al0; o[nt][1] *= al0;
            o[nt][2] *= al1; o[nt][3] *= al1;
        }

        // ---- write P (16x32) as fp16 to per-warp smem ----
#pragma unroll
        for (int nt = 0; nt < 4; nt++) {
            __half2 p0 = __floats2half2_rn(c[nt][0], c[nt][1]);
            __half2 p1 = __floats2half2_rn(c[nt][2], c[nt][3]);
            *(uint32_t*)&pw[g       * F_LP + nt * 8 + q * 2] = *(uint32_t*)&p0;
            *(uint32_t*)&pw[(g + 8) * F_LP + nt * 8 + q * 2] = *(uint32_t*)&p1;
        }
        __syncwarp();

        // ---- O += P @ V : 16 x 128 per warp (2 k-steps of 16) ----
#pragma unroll
        for (int ks16 = 0; ks16 < 2; ks16++) {
            const int kk = ks16 * 16;
            uint32_t a0 = *(const uint32_t*)&pw[g       * F_LP + kk + 2 * q];
            uint32_t a1 = *(const uint32_t*)&pw[(g + 8) * F_LP + kk + 2 * q];
            uint32_t a2 = *(const uint32_t*)&pw[g       * F_LP + kk + 2 * q + 8];
            uint32_t a3 = *(const uint32_t*)&pw[(g + 8) * F_LP + kk + 2 * q + 8];
#pragma unroll
            for (int nt = 0; nt < 16; nt++) {
                uint32_t b0 = *(const uint32_t*)&vs[(nt * 8 + g) * F_LVT + kk + 2 * q];
                uint32_t b1 = *(const uint32_t*)&vs[(nt * 8 + g) * F_LVT + kk + 2 * q + 8];
                MMA_F16(o[nt], a0, a1, a2, a3, b0, b1);
            }
        }

        // ---- stage V(j+1) into the other buffer ----
        if (pf) sts_v_transposed(vbuf[(j + 1) & 1], nv0, nv1, tid);
        __syncthreads();
    }

    // ---- epilogue: O / l -> g_at fp16 (B,S,DIM) for the output GEMM ----
    const float inv0 = 1.0f / l0, inv1 = 1.0f / l1;
    __half* ob0 = g_at + (b * SS + row0g) * DIMM + h * HDD;
    __half* ob1 = g_at + (b * SS + row1g) * DIMM + h * HDD;
#pragma unroll
    for (int nt = 0; nt < 16; nt++) {
        const int d = nt * 8 + q * 2;
        __half2 h0 = __floats2half2_rn(o[nt][0] * inv0, o[nt][1] * inv0);
        __half2 h1 = __floats2half2_rn(o[nt][2] * inv1, o[nt][3] * inv1);
        *(uint32_t*)&ob0[d] = *(uint32_t*)&h0;
        *(uint32_t*)&ob1[d] = *(uint32_t*)&h1;
    }
}

// =============================== launch =====================================
extern "C" void kernel_launch(void* const* d_in, const int* in_sizes, int n_in,
                              void* d_out, int out_size) {
    (void)in_sizes; (void)n_in; (void)out_size;
    const float* x  = (const float*)d_in[0];
    const float* ct = (const float*)d_in[1];
    const float* st = (const float*)d_in[2];
    // d_in[3] = causal mask — implemented analytically
    const float* wq = (const float*)d_in[4];
    const float* wk = (const float*)d_in[5];
    const float* wv = (const float*)d_in[6];
    const float* wo = (const float*)d_in[7];
    const float* qw = (const float*)d_in[8];
    const float* kw = (const float*)d_in[9];
    float* out = (float*)d_out;

    cudaFuncSetAttribute(gemm_qk,  cudaFuncAttributeMaxDynamicSharedMemorySize, G_SMEM_BYTES);
    cudaFuncSetAttribute(gemm_v,   cudaFuncAttributeMaxDynamicSharedMemorySize, G_SMEM_BYTES);
    cudaFuncSetAttribute(gemm_out, cudaFuncAttributeMaxDynamicSharedMemorySize, G_SMEM_BYTES);
    cudaFuncSetAttribute(flash_attn, cudaFuncAttributeMaxDynamicSharedMemorySize,
                         F_SM_HALVES * 2);

    __half* gat;  cudaGetSymbolAddress((void**)&gat, g_at);
    __half* gw;   cudaGetSymbolAddress((void**)&gw,  g_w);

    // ---- prepass: convert X and all weights to fp16 scratch ----
    round_copy_h<<<(MM * DIMM / 8) / 256, 256>>>(x,  gat,          MM * DIMM / 8);
    round_copy_h<<<(WSZ / 8) / 256, 256>>>(wq, gw + 0 * WSZ, WSZ / 8);
    round_copy_h<<<(WSZ / 8) / 256, 256>>>(wk, gw + 1 * WSZ, WSZ / 8);
    round_copy_h<<<(WSZ / 8) / 256, 256>>>(wv, gw + 2 * WSZ, WSZ / 8);
    round_copy_h<<<(WSZ / 8) / 256, 256>>>(wo, gw + 3 * WSZ, WSZ / 8);

    const dim3 gGrid(DIMM / G_BN, MM / G_BM);   // (16, 64)

    gemm_qk<<<gGrid, 256, G_SMEM_BYTES>>>(qw, ct, st, 0);
    gemm_qk<<<gGrid, 256, G_SMEM_BYTES>>>(kw, ct, st, 1);
    gemm_v <<<gGrid, 256, G_SMEM_BYTES>>>();

    flash_attn<<<dim3(SS / F_QT, BB * HH), 256, F_SM_HALVES * 2>>>();

    gemm_out<<<gGrid, 256, G_SMEM_BYTES>>>(out);
}